// round 1
// baseline (speedup 1.0000x reference)
#include <cuda_runtime.h>
#include <cstdint>

// ---------------- problem constants (fixed for this instance) ----------------
#define T_MAX   8192
#define E_DIM   1280
#define NHEADS  20
#define HDIM    64

// ---------------- scratch (static __device__, no allocation) -----------------
__device__ float g_h[T_MAX * E_DIM];
__device__ float g_q[T_MAX * E_DIM];
__device__ float g_k[T_MAX * E_DIM];
__device__ float g_v[T_MAX * E_DIM];
__device__ float g_o[T_MAX * E_DIM];

// ---------------- small PTX helpers ----------------
__device__ __forceinline__ uint32_t f2tf(float x) {
    uint32_t r;
    asm("cvt.rna.tf32.f32 %0, %1;" : "=r"(r) : "f"(x));
    return r;
}

__device__ __forceinline__ void mma_tf32(float (&c)[4],
                                         uint32_t a0, uint32_t a1, uint32_t a2, uint32_t a3,
                                         uint32_t b0, uint32_t b1) {
    asm volatile(
        "mma.sync.aligned.m16n8k8.row.col.f32.tf32.tf32.f32 "
        "{%0,%1,%2,%3},{%4,%5,%6,%7},{%8,%9},{%0,%1,%2,%3};"
        : "+f"(c[0]), "+f"(c[1]), "+f"(c[2]), "+f"(c[3])
        : "r"(a0), "r"(a1), "r"(a2), "r"(a3), "r"(b0), "r"(b1));
}

__device__ __forceinline__ void cp16(void* smem, const void* gmem) {
    uint32_t s = (uint32_t)__cvta_generic_to_shared(smem);
    asm volatile("cp.async.cg.shared.global [%0], [%1], 16;" :: "r"(s), "l"(gmem));
}
__device__ __forceinline__ void cp_commit() { asm volatile("cp.async.commit_group;"); }
__device__ __forceinline__ void cp_wait1()  { asm volatile("cp.async.wait_group 1;"); }
__device__ __forceinline__ void cp_wait0()  { asm volatile("cp.async.wait_group 0;"); }

// ---------------- LayerNorm (with optional bias) ----------------
// one block per row; smem row staging so output can alias input
__global__ void ln_kernel(const float* __restrict__ in, float* __restrict__ out,
                          const float* __restrict__ w, const float* __restrict__ b, int E) {
    extern __shared__ float srow[];
    int row = blockIdx.x;
    const float* x = in + (size_t)row * E;
    float s = 0.f, ss = 0.f;
    for (int i = threadIdx.x; i < E; i += blockDim.x) {
        float v = x[i];
        srow[i] = v;
        s += v; ss += v * v;
    }
    __shared__ float red[64];
    for (int o = 16; o; o >>= 1) {
        s  += __shfl_xor_sync(0xffffffffu, s,  o);
        ss += __shfl_xor_sync(0xffffffffu, ss, o);
    }
    int wid = threadIdx.x >> 5, lane = threadIdx.x & 31;
    if (lane == 0) { red[wid] = s; red[32 + wid] = ss; }
    __syncthreads();
    if (wid == 0) {
        int nw = blockDim.x >> 5;
        s  = (lane < nw) ? red[lane]      : 0.f;
        ss = (lane < nw) ? red[32 + lane] : 0.f;
        for (int o = 16; o; o >>= 1) {
            s  += __shfl_xor_sync(0xffffffffu, s,  o);
            ss += __shfl_xor_sync(0xffffffffu, ss, o);
        }
        if (lane == 0) { red[0] = s; red[1] = ss; }
    }
    __syncthreads();
    float mean = red[0] / (float)E;
    float var  = red[1] / (float)E - mean * mean;
    float inv  = rsqrtf(var + 1e-5f);
    float* op = out + (size_t)row * E;
    for (int i = threadIdx.x; i < E; i += blockDim.x) {
        float y = (srow[i] - mean) * inv * w[i];
        if (b) y += b[i];
        op[i] = y;
    }
}

// ---------------- LayerNorm (no bias) + RoPE, in-place ----------------
__global__ void lnrope_kernel(float* __restrict__ q, const float* __restrict__ w,
                              const int* __restrict__ cu, int B, int E) {
    extern __shared__ float srow[];
    int row = blockIdx.x;
    float* x = q + (size_t)row * E;
    float s = 0.f, ss = 0.f;
    for (int i = threadIdx.x; i < E; i += blockDim.x) {
        float v = x[i];
        srow[i] = v;
        s += v; ss += v * v;
    }
    __shared__ float red[64];
    for (int o = 16; o; o >>= 1) {
        s  += __shfl_xor_sync(0xffffffffu, s,  o);
        ss += __shfl_xor_sync(0xffffffffu, ss, o);
    }
    int wid = threadIdx.x >> 5, lane = threadIdx.x & 31;
    if (lane == 0) { red[wid] = s; red[32 + wid] = ss; }
    __syncthreads();
    if (wid == 0) {
        int nw = blockDim.x >> 5;
        s  = (lane < nw) ? red[lane]      : 0.f;
        ss = (lane < nw) ? red[32 + lane] : 0.f;
        for (int o = 16; o; o >>= 1) {
            s  += __shfl_xor_sync(0xffffffffu, s,  o);
            ss += __shfl_xor_sync(0xffffffffu, ss, o);
        }
        if (lane == 0) { red[0] = s; red[1] = ss; }
    }
    __syncthreads();
    float mean = red[0] / (float)E;
    float var  = red[1] / (float)E - mean * mean;
    float inv  = rsqrtf(var + 1e-5f);

    // position within the sequence (cu_lens restart)
    int seg = 0;
    for (int i = 1; i < B; i++) if (row >= cu[i]) seg = i;
    float pos = (float)(row - cu[seg]);

    const int half = HDIM / 2;
    for (int i = threadIdx.x; i < E; i += blockDim.x) {
        int d = i % HDIM;
        int fi = (d < half) ? d : d - half;
        // inv_freq = 10000^(-2*fi/64); angle reduced in double for accuracy
        float invf = exp2f((float)fi * (-2.0f / (float)HDIM) * 13.28771237954945f);
        double ang = (double)pos * (double)invf;
        double kk  = rint(ang * 0.15915494309189535);
        float ar   = (float)(ang - kk * 6.283185307179586);
        float c = cosf(ar), sn = sinf(ar);

        float xn = (srow[i] - mean) * inv * w[i];
        int pidx = (d < half) ? (i + half) : (i - half);
        float xp = (srow[pidx] - mean) * inv * w[pidx];
        float rot = (d < half) ? -xp : xp;
        x[i] = xn * c + rot * sn;
    }
}

// ---------------- tf32 GEMM: C[M,N] = A[M,K] * B[N,K]^T ----------------
// 128x128x32 tiles, 256 threads (8 warps, warp tile 32x64), cp.async 2-stage
#define GBM 128
#define GBN 128
#define GBK 32
#define GLD 36   // smem row stride (floats), pad for conflicts + 16B alignment

__global__ __launch_bounds__(256) void gemm_tf32_kernel(
    const float* __restrict__ A, const float* __restrict__ Bw,
    float* __restrict__ C, int M, int N, int K) {
    extern __shared__ float sm[];
    float* As = sm;                 // 2 stages * 128*36
    float* Bs = sm + 2 * GBM * GLD;

    int tid = threadIdx.x, lane = tid & 31, warp = tid >> 5;
    int g = lane >> 2, t4 = lane & 3;
    int wm = (warp >> 1) * 32;      // warp m offset (0,32,64,96)
    int wn = (warp & 1) * 64;       // warp n offset (0,64)
    int bm = blockIdx.y * GBM, bn = blockIdx.x * GBN;

    float acc[2][8][4];
    #pragma unroll
    for (int mi = 0; mi < 2; mi++)
        #pragma unroll
        for (int ni = 0; ni < 8; ni++)
            #pragma unroll
            for (int j = 0; j < 4; j++) acc[mi][ni][j] = 0.f;

    // stage 0 load
    {
        int idx = tid;
        #pragma unroll
        for (int p = 0; p < 4; p++, idx += 256) {
            int r = idx >> 3, c4 = (idx & 7) << 2;
            cp16(&As[r * GLD + c4], &A[(size_t)(bm + r) * K + c4]);
            cp16(&Bs[r * GLD + c4], &Bw[(size_t)(bn + r) * K + c4]);
        }
        cp_commit();
    }

    int buf = 0;
    int KT = K / GBK;
    for (int kt = 0; kt < KT; kt++) {
        if (kt + 1 < KT) {
            int k0 = (kt + 1) * GBK;
            int boff = (buf ^ 1) * GBM * GLD;
            int idx = tid;
            #pragma unroll
            for (int p = 0; p < 4; p++, idx += 256) {
                int r = idx >> 3, c4 = (idx & 7) << 2;
                cp16(&As[boff + r * GLD + c4], &A[(size_t)(bm + r) * K + k0 + c4]);
                cp16(&Bs[boff + r * GLD + c4], &Bw[(size_t)(bn + r) * K + k0 + c4]);
            }
            cp_commit();
            cp_wait1();
        } else {
            cp_wait0();
        }
        __syncthreads();

        const float* Ab = &As[buf * GBM * GLD];
        const float* Bb = &Bs[buf * GBN * GLD];
        #pragma unroll
        for (int ks = 0; ks < 4; ks++) {
            int k0 = ks * 8;
            uint32_t af[2][4];
            #pragma unroll
            for (int mi = 0; mi < 2; mi++) {
                int r0 = wm + mi * 16;
                af[mi][0] = f2tf(Ab[(r0 + g)     * GLD + k0 + t4]);
                af[mi][1] = f2tf(Ab[(r0 + g + 8) * GLD + k0 + t4]);
                af[mi][2] = f2tf(Ab[(r0 + g)     * GLD + k0 + t4 + 4]);
                af[mi][3] = f2tf(Ab[(r0 + g + 8) * GLD + k0 + t4 + 4]);
            }
            #pragma unroll
            for (int ni = 0; ni < 8; ni++) {
                uint32_t b0 = f2tf(Bb[(wn + ni * 8 + g) * GLD + k0 + t4]);
                uint32_t b1 = f2tf(Bb[(wn + ni * 8 + g) * GLD + k0 + t4 + 4]);
                mma_tf32(acc[0][ni], af[0][0], af[0][1], af[0][2], af[0][3], b0, b1);
                mma_tf32(acc[1][ni], af[1][0], af[1][1], af[1][2], af[1][3], b0, b1);
            }
        }
        __syncthreads();
        buf ^= 1;
    }

    // epilogue
    #pragma unroll
    for (int mi = 0; mi < 2; mi++) {
        int r0 = bm + wm + mi * 16 + g;
        #pragma unroll
        for (int ni = 0; ni < 8; ni++) {
            int c0 = bn + wn + ni * 8 + 2 * t4;
            C[(size_t)r0 * N + c0]           = acc[mi][ni][0];
            C[(size_t)r0 * N + c0 + 1]       = acc[mi][ni][1];
            C[(size_t)(r0 + 8) * N + c0]     = acc[mi][ni][2];
            C[(size_t)(r0 + 8) * N + c0 + 1] = acc[mi][ni][3];
        }
    }
}

// ---------------- flash attention (tf32 mma, online softmax) ----------------
// block = 128 threads (4 warps); each block: one (64-row q tile, head, seq)
// warp w owns q rows [w*16, w*16+16)
#define ALD 68   // smem row stride

__global__ __launch_bounds__(128) void attn_kernel(
    const float* __restrict__ q, const float* __restrict__ k,
    const float* __restrict__ v, float* __restrict__ o,
    int S, int E) {
    int qt = blockIdx.x, h = blockIdx.y, b = blockIdx.z;
    extern __shared__ float sm[];
    float* Qs = sm;
    float* Ks = Qs + 64 * ALD;
    float* Vs = Ks + 64 * ALD;
    float* Ps = Vs + 64 * ALD;

    int tid = threadIdx.x, lane = tid & 31, warp = tid >> 5;
    int g = lane >> 2, t4 = lane & 3;

    size_t base = ((size_t)b * S) * (size_t)E + (size_t)h * HDIM;

    // load Q tile (64 x 64)
    for (int i = tid; i < 64 * 16; i += 128) {
        int r = i >> 4, c4 = (i & 15) << 2;
        *(float4*)&Qs[r * ALD + c4] =
            *(const float4*)&q[base + (size_t)(qt * 64 + r) * E + c4];
    }

    float mx[2] = {-1e30f, -1e30f}, l[2] = {0.f, 0.f};
    float acc[8][4];
    #pragma unroll
    for (int ni = 0; ni < 8; ni++)
        #pragma unroll
        for (int j = 0; j < 4; j++) acc[ni][j] = 0.f;

    const float scale = 0.125f;   // 64^-0.5
    int nkt = S / 64;
    for (int kt = 0; kt < nkt; kt++) {
        __syncthreads();
        for (int i = tid; i < 64 * 16; i += 128) {
            int r = i >> 4, c4 = (i & 15) << 2;
            *(float4*)&Ks[r * ALD + c4] =
                *(const float4*)&k[base + (size_t)(kt * 64 + r) * E + c4];
            *(float4*)&Vs[r * ALD + c4] =
                *(const float4*)&v[base + (size_t)(kt * 64 + r) * E + c4];
        }
        __syncthreads();

        // S = Q K^T  (warp rows: warp*16..+16, cols 0..63)
        float sf[8][4];
        #pragma unroll
        for (int ni = 0; ni < 8; ni++)
            #pragma unroll
            for (int j = 0; j < 4; j++) sf[ni][j] = 0.f;
        #pragma unroll
        for (int ks = 0; ks < 8; ks++) {
            int k0 = ks * 8;
            int r0 = warp * 16;
            uint32_t a0 = f2tf(Qs[(r0 + g)     * ALD + k0 + t4]);
            uint32_t a1 = f2tf(Qs[(r0 + g + 8) * ALD + k0 + t4]);
            uint32_t a2 = f2tf(Qs[(r0 + g)     * ALD + k0 + t4 + 4]);
            uint32_t a3 = f2tf(Qs[(r0 + g + 8) * ALD + k0 + t4 + 4]);
            #pragma unroll
            for (int ni = 0; ni < 8; ni++) {
                uint32_t b0 = f2tf(Ks[(ni * 8 + g) * ALD + k0 + t4]);
                uint32_t b1 = f2tf(Ks[(ni * 8 + g) * ALD + k0 + t4 + 4]);
                mma_tf32(sf[ni], a0, a1, a2, a3, b0, b1);
            }
        }

        // online softmax
        float rmax[2] = {-1e30f, -1e30f};
        #pragma unroll
        for (int ni = 0; ni < 8; ni++)
            #pragma unroll
            for (int j = 0; j < 4; j++) {
                sf[ni][j] *= scale;
                float& m = rmax[j >> 1];
                m = fmaxf(m, sf[ni][j]);
            }
        #pragma unroll
        for (int off = 1; off <= 2; off <<= 1) {
            rmax[0] = fmaxf(rmax[0], __shfl_xor_sync(0xffffffffu, rmax[0], off));
            rmax[1] = fmaxf(rmax[1], __shfl_xor_sync(0xffffffffu, rmax[1], off));
        }
        float mn0 = fmaxf(mx[0], rmax[0]);
        float mn1 = fmaxf(mx[1], rmax[1]);
        float c0 = __expf(mx[0] - mn0);
        float c1 = __expf(mx[1] - mn1);
        mx[0] = mn0; mx[1] = mn1;

        float rs[2] = {0.f, 0.f};
        #pragma unroll
        for (int ni = 0; ni < 8; ni++)
            #pragma unroll
            for (int j = 0; j < 4; j++) {
                float p = __expf(sf[ni][j] - ((j < 2) ? mn0 : mn1));
                sf[ni][j] = p;
                rs[j >> 1] += p;
            }
        #pragma unroll
        for (int off = 1; off <= 2; off <<= 1) {
            rs[0] += __shfl_xor_sync(0xffffffffu, rs[0], off);
            rs[1] += __shfl_xor_sync(0xffffffffu, rs[1], off);
        }
        l[0] = l[0] * c0 + rs[0];
        l[1] = l[1] * c1 + rs[1];
        #pragma unroll
        for (int ni = 0; ni < 8; ni++) {
            acc[ni][0] *= c0; acc[ni][1] *= c0;
            acc[ni][2] *= c1; acc[ni][3] *= c1;
        }

        // P -> smem (per-warp region, layout [64][64])
        {
            int r0 = warp * 16 + g;
            #pragma unroll
            for (int ni = 0; ni < 8; ni++) {
                Ps[r0 * ALD + ni * 8 + 2 * t4]           = sf[ni][0];
                Ps[r0 * ALD + ni * 8 + 2 * t4 + 1]       = sf[ni][1];
                Ps[(r0 + 8) * ALD + ni * 8 + 2 * t4]     = sf[ni][2];
                Ps[(r0 + 8) * ALD + ni * 8 + 2 * t4 + 1] = sf[ni][3];
            }
        }
        __syncwarp();

        // O += P V
        #pragma unroll
        for (int ks = 0; ks < 8; ks++) {
            int k0 = ks * 8;
            int r0 = warp * 16;
            uint32_t a0 = f2tf(Ps[(r0 + g)     * ALD + k0 + t4]);
            uint32_t a1 = f2tf(Ps[(r0 + g + 8) * ALD + k0 + t4]);
            uint32_t a2 = f2tf(Ps[(r0 + g)     * ALD + k0 + t4 + 4]);
            uint32_t a3 = f2tf(Ps[(r0 + g + 8) * ALD + k0 + t4 + 4]);
            #pragma unroll
            for (int ni = 0; ni < 8; ni++) {
                uint32_t b0 = f2tf(Vs[(k0 + t4)     * ALD + ni * 8 + g]);
                uint32_t b1 = f2tf(Vs[(k0 + t4 + 4) * ALD + ni * 8 + g]);
                mma_tf32(acc[ni], a0, a1, a2, a3, b0, b1);
            }
        }
    }

    // epilogue: normalize + store
    float i0 = 1.f / l[0], i1 = 1.f / l[1];
    int grow = qt * 64 + warp * 16 + g;
    size_t orow0 = ((size_t)b * S + grow) * E + (size_t)h * HDIM;
    size_t orow1 = ((size_t)b * S + grow + 8) * E + (size_t)h * HDIM;
    #pragma unroll
    for (int ni = 0; ni < 8; ni++) {
        int col = ni * 8 + 2 * t4;
        o[orow0 + col]     = acc[ni][0] * i0;
        o[orow0 + col + 1] = acc[ni][1] * i0;
        o[orow1 + col]     = acc[ni][2] * i1;
        o[orow1 + col + 1] = acc[ni][3] * i1;
    }
}

// ---------------- host launcher ----------------
extern "C" void kernel_launch(void* const* d_in, const int* in_sizes, int n_in,
                              void* d_out, int out_size) {
    // inputs: x, cu_lens, [max_len], norm_w, norm_b, Wq, Wk, Wv, Wout, lnq_w, lnk_w
    int idx = 0;
    const float* x  = (const float*)d_in[idx++];
    const int*  cu  = (const int*)d_in[idx++];
    if (in_sizes[idx] == 1) idx++;               // skip max_len scalar if present
    const float* norm_w = (const float*)d_in[idx++];
    const float* norm_b = (const float*)d_in[idx++];
    const float* Wq   = (const float*)d_in[idx++];
    const float* Wk   = (const float*)d_in[idx++];
    const float* Wv   = (const float*)d_in[idx++];
    const float* Wout = (const float*)d_in[idx++];
    const float* lnq  = (const float*)d_in[idx++];
    const float* lnk  = (const float*)d_in[idx++];

    const int E = E_DIM;
    const int T = in_sizes[0] / E;
    const int B = in_sizes[1] - 1;
    const int S = T / B;

    float *h, *qb, *kb, *vb, *ob;
    cudaGetSymbolAddress((void**)&h,  g_h);
    cudaGetSymbolAddress((void**)&qb, g_q);
    cudaGetSymbolAddress((void**)&kb, g_k);
    cudaGetSymbolAddress((void**)&vb, g_v);
    cudaGetSymbolAddress((void**)&ob, g_o);

    const size_t gemm_smem = 2 * (size_t)(GBM * GLD + GBN * GLD) * sizeof(float); // 73728
    const size_t attn_smem = 4 * 64 * ALD * sizeof(float);                        // 69632
    cudaFuncSetAttribute(gemm_tf32_kernel, cudaFuncAttributeMaxDynamicSharedMemorySize,
                         (int)gemm_smem);
    cudaFuncSetAttribute(attn_kernel, cudaFuncAttributeMaxDynamicSharedMemorySize,
                         (int)attn_smem);

    // 1) pre-norm
    ln_kernel<<<T, 256, E * sizeof(float)>>>(x, h, norm_w, norm_b, E);

    // 2) Q/K/V projections (h @ W^T)
    dim3 ggrid(E / GBN, T / GBM);
    gemm_tf32_kernel<<<ggrid, 256, gemm_smem>>>(h, Wq, qb, T, E, E);
    gemm_tf32_kernel<<<ggrid, 256, gemm_smem>>>(h, Wk, kb, T, E, E);
    gemm_tf32_kernel<<<ggrid, 256, gemm_smem>>>(h, Wv, vb, T, E, E);

    // 3) q/k LayerNorm + RoPE (in-place)
    lnrope_kernel<<<T, 256, E * sizeof(float)>>>(qb, lnq, cu, B, E);
    lnrope_kernel<<<T, 256, E * sizeof(float)>>>(kb, lnk, cu, B, E);

    // 4) attention
    dim3 agrid(S / 64, NHEADS, B);
    attn_kernel<<<agrid, 128, attn_smem>>>(qb, kb, vb, ob, S, E);

    // 5) output projection
    gemm_tf32_kernel<<<ggrid, 256, gemm_smem>>>(ob, Wout, (float*)d_out, T, E, E);
}

// round 4
// speedup vs baseline: 1.0808x; 1.0808x over previous
#include <cuda_runtime.h>
#include <cstdint>

// ---------------- problem constants ----------------
#define T_MAX   8192
#define E_DIM   1280
#define NHEADS  20
#define HDIM    64

// ---------------- scratch (static __device__, no allocation) -----------------
__device__ float g_h[T_MAX * E_DIM];
__device__ float g_q[T_MAX * E_DIM];
__device__ float g_k[T_MAX * E_DIM];
__device__ float g_v[T_MAX * E_DIM];
__device__ float g_o[T_MAX * E_DIM];
__device__ float g_wq[E_DIM * E_DIM];
__device__ float g_wk[E_DIM * E_DIM];
__device__ float g_wv[E_DIM * E_DIM];
__device__ float g_wo[E_DIM * E_DIM];

// ---------------- small PTX helpers ----------------
__device__ __forceinline__ uint32_t f2tf(float x) {
    uint32_t r;
    asm("cvt.rna.tf32.f32 %0, %1;" : "=r"(r) : "f"(x));
    return r;
}
__device__ __forceinline__ float rnd_tf32(float x) { return __uint_as_float(f2tf(x)); }

__device__ __forceinline__ void mma_tf32(float (&c)[4],
                                         uint32_t a0, uint32_t a1, uint32_t a2, uint32_t a3,
                                         uint32_t b0, uint32_t b1) {
    asm volatile(
        "mma.sync.aligned.m16n8k8.row.col.f32.tf32.tf32.f32 "
        "{%0,%1,%2,%3},{%4,%5,%6,%7},{%8,%9},{%0,%1,%2,%3};"
        : "+f"(c[0]), "+f"(c[1]), "+f"(c[2]), "+f"(c[3])
        : "r"(a0), "r"(a1), "r"(a2), "r"(a3), "r"(b0), "r"(b1));
}

__device__ __forceinline__ void cp16(void* smem, const void* gmem) {
    uint32_t s = (uint32_t)__cvta_generic_to_shared(smem);
    asm volatile("cp.async.cg.shared.global [%0], [%1], 16;" :: "r"(s), "l"(gmem));
}
__device__ __forceinline__ void cp_commit() { asm volatile("cp.async.commit_group;"); }
__device__ __forceinline__ void cp_wait1()  { asm volatile("cp.async.wait_group 1;"); }

// ---------------- weight rounding (fp32 -> tf32-rounded fp32) ----------------
__global__ void round_tf32_kernel(const float* __restrict__ s, float* __restrict__ d, int n) {
    int i = (blockIdx.x * 256 + threadIdx.x) * 4;
    if (i < n) {
        float4 v = *(const float4*)&s[i];
        v.x = rnd_tf32(v.x); v.y = rnd_tf32(v.y);
        v.z = rnd_tf32(v.z); v.w = rnd_tf32(v.w);
        *(float4*)&d[i] = v;
    }
}

// ---------------- LayerNorm (with optional bias), output tf32-rounded ----------------
__global__ void ln_kernel(const float* __restrict__ in, float* __restrict__ out,
                          const float* __restrict__ w, const float* __restrict__ b, int E) {
    extern __shared__ float srow[];
    int row = blockIdx.x;
    const float* x = in + (size_t)row * E;
    float s = 0.f, ss = 0.f;
    for (int i = threadIdx.x; i < E; i += blockDim.x) {
        float v = x[i];
        srow[i] = v;
        s += v; ss += v * v;
    }
    __shared__ float red[64];
    for (int o = 16; o; o >>= 1) {
        s  += __shfl_xor_sync(0xffffffffu, s,  o);
        ss += __shfl_xor_sync(0xffffffffu, ss, o);
    }
    int wid = threadIdx.x >> 5, lane = threadIdx.x & 31;
    if (lane == 0) { red[wid] = s; red[32 + wid] = ss; }
    __syncthreads();
    if (wid == 0) {
        int nw = blockDim.x >> 5;
        s  = (lane < nw) ? red[lane]      : 0.f;
        ss = (lane < nw) ? red[32 + lane] : 0.f;
        for (int o = 16; o; o >>= 1) {
            s  += __shfl_xor_sync(0xffffffffu, s,  o);
            ss += __shfl_xor_sync(0xffffffffu, ss, o);
        }
        if (lane == 0) { red[0] = s; red[1] = ss; }
    }
    __syncthreads();
    float mean = red[0] / (float)E;
    float var  = red[1] / (float)E - mean * mean;
    float inv  = rsqrtf(var + 1e-5f);
    float* op = out + (size_t)row * E;
    for (int i = threadIdx.x; i < E; i += blockDim.x) {
        float y = (srow[i] - mean) * inv * w[i];
        if (b) y += b[i];
        op[i] = rnd_tf32(y);
    }
}

// ---------------- LayerNorm (no bias) + RoPE, in-place, output tf32-rounded --------
__global__ void lnrope_kernel(float* __restrict__ q, const float* __restrict__ w,
                              const int* __restrict__ cu, int B, int E) {
    extern __shared__ float srow[];
    int row = blockIdx.x;
    float* x = q + (size_t)row * E;
    float s = 0.f, ss = 0.f;
    for (int i = threadIdx.x; i < E; i += blockDim.x) {
        float v = x[i];
        srow[i] = v;
        s += v; ss += v * v;
    }
    __shared__ float red[64];
    for (int o = 16; o; o >>= 1) {
        s  += __shfl_xor_sync(0xffffffffu, s,  o);
        ss += __shfl_xor_sync(0xffffffffu, ss, o);
    }
    int wid = threadIdx.x >> 5, lane = threadIdx.x & 31;
    if (lane == 0) { red[wid] = s; red[32 + wid] = ss; }
    __syncthreads();
    if (wid == 0) {
        int nw = blockDim.x >> 5;
        s  = (lane < nw) ? red[lane]      : 0.f;
        ss = (lane < nw) ? red[32 + lane] : 0.f;
        for (int o = 16; o; o >>= 1) {
            s  += __shfl_xor_sync(0xffffffffu, s,  o);
            ss += __shfl_xor_sync(0xffffffffu, ss, o);
        }
        if (lane == 0) { red[0] = s; red[1] = ss; }
    }
    __syncthreads();
    float mean = red[0] / (float)E;
    float var  = red[1] / (float)E - mean * mean;
    float inv  = rsqrtf(var + 1e-5f);

    int seg = 0;
    for (int i = 1; i < B; i++) if (row >= cu[i]) seg = i;
    float pos = (float)(row - cu[seg]);

    const int half = HDIM / 2;
    for (int i = threadIdx.x; i < E; i += blockDim.x) {
        int d = i % HDIM;
        int fi = (d < half) ? d : d - half;
        float invf = exp2f((float)fi * (-2.0f / (float)HDIM) * 13.28771237954945f);
        double ang = (double)pos * (double)invf;
        double kk  = rint(ang * 0.15915494309189535);
        float ar   = (float)(ang - kk * 6.283185307179586);
        float c = cosf(ar), sn = sinf(ar);

        float xn = (srow[i] - mean) * inv * w[i];
        int pidx = (d < half) ? (i + half) : (i - half);
        float xp = (srow[pidx] - mean) * inv * w[pidx];
        float rot = (d < half) ? -xp : xp;
        x[i] = rnd_tf32(xn * c + rot * sn);
    }
}

// ---------------- tf32 GEMM: C[M,N] = A[M,K] * B[N,K]^T ----------------
// Inputs MUST be pre-rounded to tf32 (raw-bit operand feed, no cvt in loop).
// Block 128x128, 4 warps (warp tile 64x64), k-tile 32, 3-stage cp.async.
#define GBM 128
#define GBN 128
#define GBK 32
#define GLD 36                      // padded row stride (floats)
#define GSTG 3
#define GSSZ ((GBM + GBN) * GLD)    // floats per stage = 9216
#define GEMM_SMEM (GSTG * GSSZ * sizeof(float))   // 110592 B

__global__ __launch_bounds__(128) void gemm_tf32_kernel(
    const float* __restrict__ A, const float* __restrict__ Bw,
    float* __restrict__ C, int M, int N, int K, int rnd) {
    extern __shared__ float sm[];
    int tid = threadIdx.x, lane = tid & 31, warp = tid >> 5;
    int g = lane >> 2, t4 = lane & 3;
    int wm = (warp >> 1) * 64;      // warp m offset (0,64)
    int wn = (warp & 1) * 64;       // warp n offset (0,64)
    int bm = blockIdx.y * GBM, bn = blockIdx.x * GBN;

    float acc[4][8][4];
    #pragma unroll
    for (int mi = 0; mi < 4; mi++)
        #pragma unroll
        for (int ni = 0; ni < 8; ni++)
            #pragma unroll
            for (int j = 0; j < 4; j++) acc[mi][ni][j] = 0.f;

    auto load_stage = [&](int st, int kt) {
        int k0 = kt * GBK;
        float* As = sm + st * GSSZ;
        float* Bs = As + GBM * GLD;
        #pragma unroll
        for (int p = 0; p < 8; p++) {
            int i = tid + p * 128;
            int r = i >> 3, c = (i & 7) << 2;
            cp16(&As[r * GLD + c], &A[(size_t)(bm + r) * K + k0 + c]);
            cp16(&Bs[r * GLD + c], &Bw[(size_t)(bn + r) * K + k0 + c]);
        }
    };

    const int KT = K / GBK;
    load_stage(0, 0); cp_commit();
    load_stage(1, 1); cp_commit();

    int st = 0;
    for (int kt = 0; kt < KT; kt++) {
        cp_wait1();            // group kt complete (<=1 pending after)
        __syncthreads();       // all warps see data kt; all done with stage being overwritten
        if (kt + 2 < KT) load_stage((st + 2) % GSTG, kt + 2);
        cp_commit();

        const float* As = sm + st * GSSZ;
        const float* Bs = As + GBM * GLD;
        #pragma unroll
        for (int ks = 0; ks < 4; ks++) {
            int k0 = ks * 8;
            uint32_t af[4][4];
            #pragma unroll
            for (int mi = 0; mi < 4; mi++) {
                int r0 = wm + mi * 16;
                af[mi][0] = __float_as_uint(As[(r0 + g)     * GLD + k0 + t4]);
                af[mi][1] = __float_as_uint(As[(r0 + g + 8) * GLD + k0 + t4]);
                af[mi][2] = __float_as_uint(As[(r0 + g)     * GLD + k0 + t4 + 4]);
                af[mi][3] = __float_as_uint(As[(r0 + g + 8) * GLD + k0 + t4 + 4]);
            }
            #pragma unroll
            for (int ni = 0; ni < 8; ni++) {
                uint32_t b0 = __float_as_uint(Bs[(wn + ni * 8 + g) * GLD + k0 + t4]);
                uint32_t b1 = __float_as_uint(Bs[(wn + ni * 8 + g) * GLD + k0 + t4 + 4]);
                #pragma unroll
                for (int mi = 0; mi < 4; mi++)
                    mma_tf32(acc[mi][ni], af[mi][0], af[mi][1], af[mi][2], af[mi][3], b0, b1);
            }
        }
        st = (st + 1) % GSTG;
    }

    // epilogue (optionally tf32-round for mma consumers downstream)
    #pragma unroll
    for (int mi = 0; mi < 4; mi++) {
        int r0 = bm + wm + mi * 16 + g;
        #pragma unroll
        for (int ni = 0; ni < 8; ni++) {
            int c0 = bn + wn + ni * 8 + 2 * t4;
            float v0 = acc[mi][ni][0], v1 = acc[mi][ni][1];
            float v2 = acc[mi][ni][2], v3 = acc[mi][ni][3];
            if (rnd) { v0 = rnd_tf32(v0); v1 = rnd_tf32(v1); v2 = rnd_tf32(v2); v3 = rnd_tf32(v3); }
            *(float2*)&C[(size_t)r0 * N + c0]       = make_float2(v0, v1);
            *(float2*)&C[(size_t)(r0 + 8) * N + c0] = make_float2(v2, v3);
        }
    }
}

// ---------------- flash attention (tf32 mma, online softmax) ----------------
// Inputs q/k/v pre-rounded to tf32. Double-buffered cp.async K/V tiles.
#define ALD 68
#define ATT_SMEM (6 * 64 * ALD * sizeof(float))   // Q + P + 2*(K+V) = 104448 B

__global__ __launch_bounds__(128) void attn_kernel(
    const float* __restrict__ q, const float* __restrict__ k,
    const float* __restrict__ v, float* __restrict__ o,
    int S, int E) {
    int qt = blockIdx.x, h = blockIdx.y, b = blockIdx.z;
    extern __shared__ float sm[];
    float* Qs = sm;                       // 64 x ALD
    float* Ps = sm + 64 * ALD;            // 64 x ALD
    float* KV = sm + 2 * 64 * ALD;        // stage s: K at s*2*64*ALD, V at +64*ALD

    int tid = threadIdx.x, lane = tid & 31, warp = tid >> 5;
    int g = lane >> 2, t4 = lane & 3;

    size_t base = ((size_t)b * S) * (size_t)E + (size_t)h * HDIM;

    // load Q tile (64 x 64) directly
    for (int i = tid; i < 64 * 16; i += 128) {
        int r = i >> 4, c4 = (i & 15) << 2;
        *(float4*)&Qs[r * ALD + c4] =
            *(const float4*)&q[base + (size_t)(qt * 64 + r) * E + c4];
    }

    auto load_kv = [&](int s, int kt) {
        float* Ks = KV + s * 2 * 64 * ALD;
        float* Vs = Ks + 64 * ALD;
        #pragma unroll
        for (int p = 0; p < 8; p++) {
            int i = tid + p * 128;
            int r = i >> 4, c4 = (i & 15) << 2;
            cp16(&Ks[r * ALD + c4], &k[base + (size_t)(kt * 64 + r) * E + c4]);
            cp16(&Vs[r * ALD + c4], &v[base + (size_t)(kt * 64 + r) * E + c4]);
        }
    };

    float mx[2] = {-1e30f, -1e30f}, l[2] = {0.f, 0.f};
    float acc[8][4];
    #pragma unroll
    for (int ni = 0; ni < 8; ni++)
        #pragma unroll
        for (int j = 0; j < 4; j++) acc[ni][j] = 0.f;

    const float scale = 0.125f;   // 64^-0.5
    int nkt = S / 64;

    load_kv(0, 0); cp_commit();

    for (int kt = 0; kt < nkt; kt++) {
        __syncthreads();          // all warps done with the buffer we're about to overwrite
        if (kt + 1 < nkt) load_kv((kt + 1) & 1, kt + 1);
        cp_commit();
        cp_wait1();               // tile kt complete
        __syncthreads();

        const float* Ks = KV + (kt & 1) * 2 * 64 * ALD;
        const float* Vs = Ks + 64 * ALD;

        // S = Q K^T
        float sf[8][4];
        #pragma unroll
        for (int ni = 0; ni < 8; ni++)
            #pragma unroll
            for (int j = 0; j < 4; j++) sf[ni][j] = 0.f;
        #pragma unroll
        for (int ks = 0; ks < 8; ks++) {
            int k0 = ks * 8;
            int r0 = warp * 16;
            uint32_t a0 = __float_as_uint(Qs[(r0 + g)     * ALD + k0 + t4]);
            uint32_t a1 = __float_as_uint(Qs[(r0 + g + 8) * ALD + k0 + t4]);
            uint32_t a2 = __float_as_uint(Qs[(r0 + g)     * ALD + k0 + t4 + 4]);
            uint32_t a3 = __float_as_uint(Qs[(r0 + g + 8) * ALD + k0 + t4 + 4]);
            #pragma unroll
            for (int ni = 0; ni < 8; ni++) {
                uint32_t b0 = __float_as_uint(Ks[(ni * 8 + g) * ALD + k0 + t4]);
                uint32_t b1 = __float_as_uint(Ks[(ni * 8 + g) * ALD + k0 + t4 + 4]);
                mma_tf32(sf[ni], a0, a1, a2, a3, b0, b1);
            }
        }

        // online softmax
        float rmax[2] = {-1e30f, -1e30f};
        #pragma unroll
        for (int ni = 0; ni < 8; ni++)
            #pragma unroll
            for (int j = 0; j < 4; j++) {
                sf[ni][j] *= scale;
                float& m = rmax[j >> 1];
                m = fmaxf(m, sf[ni][j]);
            }
        #pragma unroll
        for (int off = 1; off <= 2; off <<= 1) {
            rmax[0] = fmaxf(rmax[0], __shfl_xor_sync(0xffffffffu, rmax[0], off));
            rmax[1] = fmaxf(rmax[1], __shfl_xor_sync(0xffffffffu, rmax[1], off));
        }
        float mn0 = fmaxf(mx[0], rmax[0]);
        float mn1 = fmaxf(mx[1], rmax[1]);
        float c0 = __expf(mx[0] - mn0);
        float c1 = __expf(mx[1] - mn1);
        mx[0] = mn0; mx[1] = mn1;

        float rs[2] = {0.f, 0.f};
        #pragma unroll
        for (int ni = 0; ni < 8; ni++)
            #pragma unroll
            for (int j = 0; j < 4; j++) {
                float p = __expf(sf[ni][j] - ((j < 2) ? mn0 : mn1));
                sf[ni][j] = p;
                rs[j >> 1] += p;
            }
        #pragma unroll
        for (int off = 1; off <= 2; off <<= 1) {
            rs[0] += __shfl_xor_sync(0xffffffffu, rs[0], off);
            rs[1] += __shfl_xor_sync(0xffffffffu, rs[1], off);
        }
        l[0] = l[0] * c0 + rs[0];
        l[1] = l[1] * c1 + rs[1];
        #pragma unroll
        for (int ni = 0; ni < 8; ni++) {
            acc[ni][0] *= c0; acc[ni][1] *= c0;
            acc[ni][2] *= c1; acc[ni][3] *= c1;
        }

        // P -> smem (tf32-rounded so PV mma feeds raw bits)
        {
            int r0 = warp * 16 + g;
            #pragma unroll
            for (int ni = 0; ni < 8; ni++) {
                Ps[r0 * ALD + ni * 8 + 2 * t4]           = rnd_tf32(sf[ni][0]);
                Ps[r0 * ALD + ni * 8 + 2 * t4 + 1]       = rnd_tf32(sf[ni][1]);
                Ps[(r0 + 8) * ALD + ni * 8 + 2 * t4]     = rnd_tf32(sf[ni][2]);
                Ps[(r0 + 8) * ALD + ni * 8 + 2 * t4 + 1] = rnd_tf32(sf[ni][3]);
            }
        }
        __syncwarp();

        // O += P V
        #pragma unroll
        for (int ks = 0; ks < 8; ks++) {
            int k0 = ks * 8;
            int r0 = warp * 16;
            uint32_t a0 = __float_as_uint(Ps[(r0 + g)     * ALD + k0 + t4]);
            uint32_t a1 = __float_as_uint(Ps[(r0 + g + 8) * ALD + k0 + t4]);
            uint32_t a2 = __float_as_uint(Ps[(r0 + g)     * ALD + k0 + t4 + 4]);
            uint32_t a3 = __float_as_uint(Ps[(r0 + g + 8) * ALD + k0 + t4 + 4]);
            #pragma unroll
            for (int ni = 0; ni < 8; ni++) {
                uint32_t b0 = __float_as_uint(Vs[(k0 + t4)     * ALD + ni * 8 + g]);
                uint32_t b1 = __float_as_uint(Vs[(k0 + t4 + 4) * ALD + ni * 8 + g]);
                mma_tf32(acc[ni], a0, a1, a2, a3, b0, b1);
            }
        }
    }

    // epilogue: normalize + tf32-round (feeds the output projection)
    float i0 = 1.f / l[0], i1 = 1.f / l[1];
    int grow = qt * 64 + warp * 16 + g;
    size_t orow0 = ((size_t)b * S + grow) * E + (size_t)h * HDIM;
    size_t orow1 = ((size_t)b * S + grow + 8) * E + (size_t)h * HDIM;
    #pragma unroll
    for (int ni = 0; ni < 8; ni++) {
        int col = ni * 8 + 2 * t4;
        o[orow0 + col]     = rnd_tf32(acc[ni][0] * i0);
        o[orow0 + col + 1] = rnd_tf32(acc[ni][1] * i0);
        o[orow1 + col]     = rnd_tf32(acc[ni][2] * i1);
        o[orow1 + col + 1] = rnd_tf32(acc[ni][3] * i1);
    }
}

// ---------------- host launcher ----------------
extern "C" void kernel_launch(void* const* d_in, const int* in_sizes, int n_in,
                              void* d_out, int out_size) {
    int idx = 0;
    const float* x  = (const float*)d_in[idx++];
    const int*  cu  = (const int*)d_in[idx++];
    if (in_sizes[idx] == 1) idx++;               // skip max_len scalar if present
    const float* norm_w = (const float*)d_in[idx++];
    const float* norm_b = (const float*)d_in[idx++];
    const float* Wq   = (const float*)d_in[idx++];
    const float* Wk   = (const float*)d_in[idx++];
    const float* Wv   = (const float*)d_in[idx++];
    const float* Wout = (const float*)d_in[idx++];
    const float* lnq  = (const float*)d_in[idx++];
    const float* lnk  = (const float*)d_in[idx++];

    const int E = E_DIM;
    const int T = in_sizes[0] / E;
    const int B = in_sizes[1] - 1;
    const int S = T / B;

    float *h, *qb, *kb, *vb, *ob, *wq, *wk, *wv, *wo;
    cudaGetSymbolAddress((void**)&h,  g_h);
    cudaGetSymbolAddress((void**)&qb, g_q);
    cudaGetSymbolAddress((void**)&kb, g_k);
    cudaGetSymbolAddress((void**)&vb, g_v);
    cudaGetSymbolAddress((void**)&ob, g_o);
    cudaGetSymbolAddress((void**)&wq, g_wq);
    cudaGetSymbolAddress((void**)&wk, g_wk);
    cudaGetSymbolAddress((void**)&wv, g_wv);
    cudaGetSymbolAddress((void**)&wo, g_wo);

    cudaFuncSetAttribute(gemm_tf32_kernel, cudaFuncAttributeMaxDynamicSharedMemorySize,
                         (int)GEMM_SMEM);
    cudaFuncSetAttribute(attn_kernel, cudaFuncAttributeMaxDynamicSharedMemorySize,
                         (int)ATT_SMEM);

    // 0) tf32-round weight copies (moves all cvt out of the GEMM hot loops)
    int wgrid = (E * E) / 1024;
    round_tf32_kernel<<<wgrid, 256>>>(Wq,   wq, E * E);
    round_tf32_kernel<<<wgrid, 256>>>(Wk,   wk, E * E);
    round_tf32_kernel<<<wgrid, 256>>>(Wv,   wv, E * E);
    round_tf32_kernel<<<wgrid, 256>>>(Wout, wo, E * E);

    // 1) pre-norm (output tf32-rounded)
    ln_kernel<<<T, 256, E * sizeof(float)>>>(x, h, norm_w, norm_b, E);

    // 2) Q/K/V projections; V output rounded (feeds PV mma directly)
    dim3 ggrid(E / GBN, T / GBM);
    gemm_tf32_kernel<<<ggrid, 128, GEMM_SMEM>>>(h, wq, qb, T, E, E, 0);
    gemm_tf32_kernel<<<ggrid, 128, GEMM_SMEM>>>(h, wk, kb, T, E, E, 0);
    gemm_tf32_kernel<<<ggrid, 128, GEMM_SMEM>>>(h, wv, vb, T, E, E, 1);

    // 3) q/k LayerNorm + RoPE (in-place, outputs tf32-rounded)
    lnrope_kernel<<<T, 256, E * sizeof(float)>>>(qb, lnq, cu, B, E);
    lnrope_kernel<<<T, 256, E * sizeof(float)>>>(kb, lnk, cu, B, E);

    // 4) attention
    dim3 agrid(S / 64, NHEADS, B);
    attn_kernel<<<agrid, 128, ATT_SMEM>>>(qb, kb, vb, ob, S, E);

    // 5) output projection (plain fp32 output)
    gemm_tf32_kernel<<<ggrid, 128, GEMM_SMEM>>>(ob, wo, (float*)d_out, T, E, E, 0);
}

// round 5
// speedup vs baseline: 1.1273x; 1.0431x over previous
#include <cuda_runtime.h>
#include <cstdint>

// ---------------- problem constants ----------------
#define T_MAX   8192
#define E_DIM   1280
#define NHEADS  20
#define HDIM    64

// ---------------- scratch (static __device__, no allocation) -----------------
__device__ float g_h[T_MAX * E_DIM];
__device__ float g_q[T_MAX * E_DIM];
__device__ float g_k[T_MAX * E_DIM];
__device__ float g_v[T_MAX * E_DIM];
__device__ float g_o[T_MAX * E_DIM];
__device__ float g_wq[E_DIM * E_DIM];
__device__ float g_wk[E_DIM * E_DIM];
__device__ float g_wv[E_DIM * E_DIM];
__device__ float g_wo[E_DIM * E_DIM];

// ---------------- small PTX helpers ----------------
__device__ __forceinline__ uint32_t f2tf(float x) {
    uint32_t r;
    asm("cvt.rna.tf32.f32 %0, %1;" : "=r"(r) : "f"(x));
    return r;
}
__device__ __forceinline__ float rnd_tf32(float x) { return __uint_as_float(f2tf(x)); }

__device__ __forceinline__ void mma_tf32(float (&c)[4],
                                         uint32_t a0, uint32_t a1, uint32_t a2, uint32_t a3,
                                         uint32_t b0, uint32_t b1) {
    asm volatile(
        "mma.sync.aligned.m16n8k8.row.col.f32.tf32.tf32.f32 "
        "{%0,%1,%2,%3},{%4,%5,%6,%7},{%8,%9},{%0,%1,%2,%3};"
        : "+f"(c[0]), "+f"(c[1]), "+f"(c[2]), "+f"(c[3])
        : "r"(a0), "r"(a1), "r"(a2), "r"(a3), "r"(b0), "r"(b1));
}

// ldmatrix x4: 4 8x8 b16 tiles; addresses from lanes 0-7,8-15,16-23,24-31 -> r0..r3
__device__ __forceinline__ void ldsm4(uint32_t (&r)[4], uint32_t addr) {
    asm volatile("ldmatrix.sync.aligned.m8n8.x4.shared.b16 {%0,%1,%2,%3}, [%4];"
                 : "=r"(r[0]), "=r"(r[1]), "=r"(r[2]), "=r"(r[3]) : "r"(addr));
}

__device__ __forceinline__ uint32_t smem_u32(const void* p) {
    return (uint32_t)__cvta_generic_to_shared(p);
}
__device__ __forceinline__ void cp16(void* smem, const void* gmem) {
    asm volatile("cp.async.cg.shared.global [%0], [%1], 16;"
                 :: "r"(smem_u32(smem)), "l"(gmem));
}
__device__ __forceinline__ void cp_commit() { asm volatile("cp.async.commit_group;"); }
__device__ __forceinline__ void cp_wait1()  { asm volatile("cp.async.wait_group 1;"); }
__device__ __forceinline__ void cp_wait0()  { asm volatile("cp.async.wait_group 0;"); }

// ---------------- weight rounding (fp32 -> tf32-rounded fp32) ----------------
__global__ void round_tf32_kernel(const float* __restrict__ s, float* __restrict__ d, int n) {
    int i = (blockIdx.x * 256 + threadIdx.x) * 4;
    if (i < n) {
        float4 v = *(const float4*)&s[i];
        v.x = rnd_tf32(v.x); v.y = rnd_tf32(v.y);
        v.z = rnd_tf32(v.z); v.w = rnd_tf32(v.w);
        *(float4*)&d[i] = v;
    }
}

// ---------------- LayerNorm (with optional bias), output tf32-rounded ----------------
__global__ void ln_kernel(const float* __restrict__ in, float* __restrict__ out,
                          const float* __restrict__ w, const float* __restrict__ b, int E) {
    extern __shared__ float srow[];
    int row = blockIdx.x;
    const float* x = in + (size_t)row * E;
    float s = 0.f, ss = 0.f;
    for (int i = threadIdx.x; i < E; i += blockDim.x) {
        float v = x[i];
        srow[i] = v;
        s += v; ss += v * v;
    }
    __shared__ float red[64];
    for (int o = 16; o; o >>= 1) {
        s  += __shfl_xor_sync(0xffffffffu, s,  o);
        ss += __shfl_xor_sync(0xffffffffu, ss, o);
    }
    int wid = threadIdx.x >> 5, lane = threadIdx.x & 31;
    if (lane == 0) { red[wid] = s; red[32 + wid] = ss; }
    __syncthreads();
    if (wid == 0) {
        int nw = blockDim.x >> 5;
        s  = (lane < nw) ? red[lane]      : 0.f;
        ss = (lane < nw) ? red[32 + lane] : 0.f;
        for (int o = 16; o; o >>= 1) {
            s  += __shfl_xor_sync(0xffffffffu, s,  o);
            ss += __shfl_xor_sync(0xffffffffu, ss, o);
        }
        if (lane == 0) { red[0] = s; red[1] = ss; }
    }
    __syncthreads();
    float mean = red[0] / (float)E;
    float var  = red[1] / (float)E - mean * mean;
    float inv  = rsqrtf(var + 1e-5f);
    float* op = out + (size_t)row * E;
    for (int i = threadIdx.x; i < E; i += blockDim.x) {
        float y = (srow[i] - mean) * inv * w[i];
        if (b) y += b[i];
        op[i] = rnd_tf32(y);
    }
}

// ---------------- LayerNorm (no bias) + RoPE, in-place, output tf32-rounded --------
__global__ void lnrope_kernel(float* __restrict__ q, const float* __restrict__ w,
                              const int* __restrict__ cu, int B, int E) {
    extern __shared__ float srow[];
    int row = blockIdx.x;
    float* x = q + (size_t)row * E;
    float s = 0.f, ss = 0.f;
    for (int i = threadIdx.x; i < E; i += blockDim.x) {
        float v = x[i];
        srow[i] = v;
        s += v; ss += v * v;
    }
    __shared__ float red[64];
    for (int o = 16; o; o >>= 1) {
        s  += __shfl_xor_sync(0xffffffffu, s,  o);
        ss += __shfl_xor_sync(0xffffffffu, ss, o);
    }
    int wid = threadIdx.x >> 5, lane = threadIdx.x & 31;
    if (lane == 0) { red[wid] = s; red[32 + wid] = ss; }
    __syncthreads();
    if (wid == 0) {
        int nw = blockDim.x >> 5;
        s  = (lane < nw) ? red[lane]      : 0.f;
        ss = (lane < nw) ? red[32 + lane] : 0.f;
        for (int o = 16; o; o >>= 1) {
            s  += __shfl_xor_sync(0xffffffffu, s,  o);
            ss += __shfl_xor_sync(0xffffffffu, ss, o);
        }
        if (lane == 0) { red[0] = s; red[1] = ss; }
    }
    __syncthreads();
    float mean = red[0] / (float)E;
    float var  = red[1] / (float)E - mean * mean;
    float inv  = rsqrtf(var + 1e-5f);

    int seg = 0;
    for (int i = 1; i < B; i++) if (row >= cu[i]) seg = i;
    float pos = (float)(row - cu[seg]);

    const int half = HDIM / 2;
    for (int i = threadIdx.x; i < E; i += blockDim.x) {
        int d = i % HDIM;
        int fi = (d < half) ? d : d - half;
        float invf = exp2f((float)fi * (-2.0f / (float)HDIM) * 13.28771237954945f);
        double ang = (double)pos * (double)invf;
        double kk  = rint(ang * 0.15915494309189535);
        float ar   = (float)(ang - kk * 6.283185307179586);
        float c = cosf(ar), sn = sinf(ar);

        float xn = (srow[i] - mean) * inv * w[i];
        int pidx = (d < half) ? (i + half) : (i - half);
        float xp = (srow[pidx] - mean) * inv * w[pidx];
        float rot = (d < half) ? -xp : xp;
        x[i] = rnd_tf32(xn * c + rot * sn);
    }
}

// ---------------- tf32 GEMM: C[M,N] = A[M,K] * B[N,K]^T ----------------
// Inputs pre-rounded to tf32. Block 128x128, 256 threads (8 warps, warp 64x32),
// ldmatrix operand feed, 2-stage cp.async, 73.7KB smem -> 2 CTAs/SM.
#define GBM 128
#define GBN 128
#define GBK 32
#define GLD 36                      // padded row stride (floats); 144B, ldmatrix conflict-free
#define GSSZ ((GBM + GBN) * GLD)    // floats per stage = 9216
#define GEMM_SMEM (2 * GSSZ * sizeof(float))   // 73728 B

__global__ __launch_bounds__(256) void gemm_tf32_kernel(
    const float* __restrict__ A, const float* __restrict__ Bw,
    float* __restrict__ C, int M, int N, int K, int rnd) {
    extern __shared__ float sm[];
    int tid = threadIdx.x, lane = tid & 31, warp = tid >> 5;
    int g = lane >> 2, t4 = lane & 3;
    int wm = (warp & 1) * 64;       // 2 m-warps
    int wn = (warp >> 1) * 32;      // 4 n-warps
    int bm = blockIdx.y * GBM, bn = blockIdx.x * GBN;

    // per-thread ldmatrix row/col (element indices within tile)
    int arow = (lane & 7) + ((lane >> 3) & 1) * 8;   // + wm + mi*16
    int acol = (lane >> 4) * 4;
    int brow = (lane & 7) + ((lane >> 4) & 1) * 8;   // + wn + n2*16
    int bcol = ((lane >> 3) & 1) * 4;

    float acc[4][4][4];
    #pragma unroll
    for (int mi = 0; mi < 4; mi++)
        #pragma unroll
        for (int ni = 0; ni < 4; ni++)
            #pragma unroll
            for (int j = 0; j < 4; j++) acc[mi][ni][j] = 0.f;

    auto load_stage = [&](int st, int kt) {
        int k0 = kt * GBK;
        float* As = sm + st * GSSZ;
        float* Bs = As + GBM * GLD;
        #pragma unroll
        for (int p = 0; p < 4; p++) {
            int i = tid + p * 256;
            int r = i >> 3, c = (i & 7) << 2;
            cp16(&As[r * GLD + c], &A[(size_t)(bm + r) * K + k0 + c]);
            cp16(&Bs[r * GLD + c], &Bw[(size_t)(bn + r) * K + k0 + c]);
        }
    };

    const int KT = K / GBK;
    load_stage(0, 0); cp_commit();

    int buf = 0;
    for (int kt = 0; kt < KT; kt++) {
        if (kt + 1 < KT) { load_stage(buf ^ 1, kt + 1); cp_commit(); cp_wait1(); }
        else             { cp_wait0(); }
        __syncthreads();

        const float* As = sm + buf * GSSZ;
        const float* Bs = As + GBM * GLD;
        uint32_t abase[4], bbase[2];
        #pragma unroll
        for (int mi = 0; mi < 4; mi++)
            abase[mi] = smem_u32(&As[(wm + mi * 16 + arow) * GLD + acol]);
        #pragma unroll
        for (int n2 = 0; n2 < 2; n2++)
            bbase[n2] = smem_u32(&Bs[(wn + n2 * 16 + brow) * GLD + bcol]);

        #pragma unroll
        for (int ks = 0; ks < 4; ks++) {
            uint32_t af[4][4], bf[2][4];
            #pragma unroll
            for (int mi = 0; mi < 4; mi++) ldsm4(af[mi], abase[mi] + ks * 32);
            #pragma unroll
            for (int n2 = 0; n2 < 2; n2++) ldsm4(bf[n2], bbase[n2] + ks * 32);
            #pragma unroll
            for (int ni = 0; ni < 4; ni++) {
                uint32_t b0 = bf[ni >> 1][(ni & 1) * 2];
                uint32_t b1 = bf[ni >> 1][(ni & 1) * 2 + 1];
                #pragma unroll
                for (int mi = 0; mi < 4; mi++)
                    mma_tf32(acc[mi][ni], af[mi][0], af[mi][1], af[mi][2], af[mi][3], b0, b1);
            }
        }
        __syncthreads();
        buf ^= 1;
    }

    // epilogue (optionally tf32-round for mma consumers downstream)
    #pragma unroll
    for (int mi = 0; mi < 4; mi++) {
        int r0 = bm + wm + mi * 16 + g;
        #pragma unroll
        for (int ni = 0; ni < 4; ni++) {
            int c0 = bn + wn + ni * 8 + 2 * t4;
            float v0 = acc[mi][ni][0], v1 = acc[mi][ni][1];
            float v2 = acc[mi][ni][2], v3 = acc[mi][ni][3];
            if (rnd) { v0 = rnd_tf32(v0); v1 = rnd_tf32(v1); v2 = rnd_tf32(v2); v3 = rnd_tf32(v3); }
            *(float2*)&C[(size_t)r0 * N + c0]       = make_float2(v0, v1);
            *(float2*)&C[(size_t)(r0 + 8) * N + c0] = make_float2(v2, v3);
        }
    }
}

// ---------------- flash attention (tf32 mma, online softmax) ----------------
// q-tile 128 rows, 8 warps (16 rows each). ldmatrix for Q/K/P; V scalar (transposed).
#define ALD 68
#define QT_ROWS 128
#define ATT_SMEM ((QT_ROWS + QT_ROWS + 4 * 64) * ALD * sizeof(float))   // 139264 B

__global__ __launch_bounds__(256) void attn_kernel(
    const float* __restrict__ q, const float* __restrict__ k,
    const float* __restrict__ v, float* __restrict__ o,
    int S, int E) {
    int qt = blockIdx.x, h = blockIdx.y, b = blockIdx.z;
    extern __shared__ float sm[];
    float* Qs = sm;                            // 128 x ALD
    float* Ps = sm + QT_ROWS * ALD;            // 128 x ALD
    float* KV = sm + 2 * QT_ROWS * ALD;        // stage s: K at s*2*64*ALD, V at +64*ALD

    int tid = threadIdx.x, lane = tid & 31, warp = tid >> 5;
    int g = lane >> 2, t4 = lane & 3;

    // ldmatrix per-thread offsets
    int arow = (lane & 7) + ((lane >> 3) & 1) * 8;   // A-frag rows (+ warp*16)
    int acol = (lane >> 4) * 4;
    int brow = (lane & 7) + ((lane >> 4) & 1) * 8;   // B-frag rows (+ n2*16)
    int bcol = ((lane >> 3) & 1) * 4;

    size_t base = ((size_t)b * S) * (size_t)E + (size_t)h * HDIM;

    // load Q tile (128 x 64)
    for (int i = tid; i < QT_ROWS * 16; i += 256) {
        int r = i >> 4, c4 = (i & 15) << 2;
        *(float4*)&Qs[r * ALD + c4] =
            *(const float4*)&q[base + (size_t)(qt * QT_ROWS + r) * E + c4];
    }

    auto load_kv = [&](int s, int kt) {
        float* Ks = KV + s * 2 * 64 * ALD;
        float* Vs = Ks + 64 * ALD;
        #pragma unroll
        for (int p = 0; p < 4; p++) {
            int i = tid + p * 256;
            int r = i >> 4, c4 = (i & 15) << 2;
            cp16(&Ks[r * ALD + c4], &k[base + (size_t)(kt * 64 + r) * E + c4]);
            cp16(&Vs[r * ALD + c4], &v[base + (size_t)(kt * 64 + r) * E + c4]);
        }
    };

    float mx[2] = {-1e30f, -1e30f}, l[2] = {0.f, 0.f};
    float acc[8][4];
    #pragma unroll
    for (int ni = 0; ni < 8; ni++)
        #pragma unroll
        for (int j = 0; j < 4; j++) acc[ni][j] = 0.f;

    const float scale = 0.125f;   // 64^-0.5
    int nkt = S / 64;

    load_kv(0, 0); cp_commit();

    uint32_t qbase = smem_u32(&Qs[(warp * 16 + arow) * ALD + acol]);
    uint32_t pbase = smem_u32(&Ps[(warp * 16 + arow) * ALD + acol]);

    for (int kt = 0; kt < nkt; kt++) {
        __syncthreads();          // all warps done with the buffer we're about to overwrite
        if (kt + 1 < nkt) load_kv((kt + 1) & 1, kt + 1);
        cp_commit();
        cp_wait1();               // tile kt complete
        __syncthreads();

        const float* Ks = KV + (kt & 1) * 2 * 64 * ALD;
        const float* Vs = Ks + 64 * ALD;

        // S = Q K^T  (warp rows warp*16..+16, cols 0..63)
        float sf[8][4];
        #pragma unroll
        for (int ni = 0; ni < 8; ni++)
            #pragma unroll
            for (int j = 0; j < 4; j++) sf[ni][j] = 0.f;

        uint32_t kbase[4];
        #pragma unroll
        for (int n2 = 0; n2 < 4; n2++)
            kbase[n2] = smem_u32(&Ks[(n2 * 16 + brow) * ALD + bcol]);

        #pragma unroll
        for (int ks = 0; ks < 8; ks++) {
            uint32_t af[4], kf[4][4];
            ldsm4(af, qbase + ks * 32);
            #pragma unroll
            for (int n2 = 0; n2 < 4; n2++) ldsm4(kf[n2], kbase[n2] + ks * 32);
            #pragma unroll
            for (int ni = 0; ni < 8; ni++) {
                uint32_t b0 = kf[ni >> 1][(ni & 1) * 2];
                uint32_t b1 = kf[ni >> 1][(ni & 1) * 2 + 1];
                mma_tf32(sf[ni], af[0], af[1], af[2], af[3], b0, b1);
            }
        }

        // online softmax
        float rmax[2] = {-1e30f, -1e30f};
        #pragma unroll
        for (int ni = 0; ni < 8; ni++)
            #pragma unroll
            for (int j = 0; j < 4; j++) {
                sf[ni][j] *= scale;
                float& m = rmax[j >> 1];
                m = fmaxf(m, sf[ni][j]);
            }
        #pragma unroll
        for (int off = 1; off <= 2; off <<= 1) {
            rmax[0] = fmaxf(rmax[0], __shfl_xor_sync(0xffffffffu, rmax[0], off));
            rmax[1] = fmaxf(rmax[1], __shfl_xor_sync(0xffffffffu, rmax[1], off));
        }
        float mn0 = fmaxf(mx[0], rmax[0]);
        float mn1 = fmaxf(mx[1], rmax[1]);
        float c0 = __expf(mx[0] - mn0);
        float c1 = __expf(mx[1] - mn1);
        mx[0] = mn0; mx[1] = mn1;

        float rs[2] = {0.f, 0.f};
        #pragma unroll
        for (int ni = 0; ni < 8; ni++)
            #pragma unroll
            for (int j = 0; j < 4; j++) {
                float p = __expf(sf[ni][j] - ((j < 2) ? mn0 : mn1));
                sf[ni][j] = p;
                rs[j >> 1] += p;
            }
        #pragma unroll
        for (int off = 1; off <= 2; off <<= 1) {
            rs[0] += __shfl_xor_sync(0xffffffffu, rs[0], off);
            rs[1] += __shfl_xor_sync(0xffffffffu, rs[1], off);
        }
        l[0] = l[0] * c0 + rs[0];
        l[1] = l[1] * c1 + rs[1];
        #pragma unroll
        for (int ni = 0; ni < 8; ni++) {
            acc[ni][0] *= c0; acc[ni][1] *= c0;
            acc[ni][2] *= c1; acc[ni][3] *= c1;
        }

        // P -> smem (tf32-rounded so PV mma feeds raw bits)
        {
            int r0 = warp * 16 + g;
            #pragma unroll
            for (int ni = 0; ni < 8; ni++) {
                Ps[r0 * ALD + ni * 8 + 2 * t4]           = rnd_tf32(sf[ni][0]);
                Ps[r0 * ALD + ni * 8 + 2 * t4 + 1]       = rnd_tf32(sf[ni][1]);
                Ps[(r0 + 8) * ALD + ni * 8 + 2 * t4]     = rnd_tf32(sf[ni][2]);
                Ps[(r0 + 8) * ALD + ni * 8 + 2 * t4 + 1] = rnd_tf32(sf[ni][3]);
            }
        }
        __syncwarp();

        // O += P V   (V accessed transposed -> scalar loads)
        #pragma unroll
        for (int ks = 0; ks < 8; ks++) {
            int k0 = ks * 8;
            uint32_t af[4];
            ldsm4(af, pbase + ks * 32);
            #pragma unroll
            for (int ni = 0; ni < 8; ni++) {
                uint32_t b0 = __float_as_uint(Vs[(k0 + t4)     * ALD + ni * 8 + g]);
                uint32_t b1 = __float_as_uint(Vs[(k0 + t4 + 4) * ALD + ni * 8 + g]);
                mma_tf32(acc[ni], af[0], af[1], af[2], af[3], b0, b1);
            }
        }
    }

    // epilogue: normalize + tf32-round (feeds the output projection)
    float i0 = 1.f / l[0], i1 = 1.f / l[1];
    int grow = qt * QT_ROWS + warp * 16 + g;
    size_t orow0 = ((size_t)b * S + grow) * E + (size_t)h * HDIM;
    size_t orow1 = ((size_t)b * S + grow + 8) * E + (size_t)h * HDIM;
    #pragma unroll
    for (int ni = 0; ni < 8; ni++) {
        int col = ni * 8 + 2 * t4;
        o[orow0 + col]     = rnd_tf32(acc[ni][0] * i0);
        o[orow0 + col + 1] = rnd_tf32(acc[ni][1] * i0);
        o[orow1 + col]     = rnd_tf32(acc[ni][2] * i1);
        o[orow1 + col + 1] = rnd_tf32(acc[ni][3] * i1);
    }
}

// ---------------- host launcher ----------------
extern "C" void kernel_launch(void* const* d_in, const int* in_sizes, int n_in,
                              void* d_out, int out_size) {
    int idx = 0;
    const float* x  = (const float*)d_in[idx++];
    const int*  cu  = (const int*)d_in[idx++];
    if (in_sizes[idx] == 1) idx++;               // skip max_len scalar if present
    const float* norm_w = (const float*)d_in[idx++];
    const float* norm_b = (const float*)d_in[idx++];
    const float* Wq   = (const float*)d_in[idx++];
    const float* Wk   = (const float*)d_in[idx++];
    const float* Wv   = (const float*)d_in[idx++];
    const float* Wout = (const float*)d_in[idx++];
    const float* lnq  = (const float*)d_in[idx++];
    const float* lnk  = (const float*)d_in[idx++];

    const int E = E_DIM;
    const int T = in_sizes[0] / E;
    const int B = in_sizes[1] - 1;
    const int S = T / B;

    float *h, *qb, *kb, *vb, *ob, *wq, *wk, *wv, *wo;
    cudaGetSymbolAddress((void**)&h,  g_h);
    cudaGetSymbolAddress((void**)&qb, g_q);
    cudaGetSymbolAddress((void**)&kb, g_k);
    cudaGetSymbolAddress((void**)&vb, g_v);
    cudaGetSymbolAddress((void**)&ob, g_o);
    cudaGetSymbolAddress((void**)&wq, g_wq);
    cudaGetSymbolAddress((void**)&wk, g_wk);
    cudaGetSymbolAddress((void**)&wv, g_wv);
    cudaGetSymbolAddress((void**)&wo, g_wo);

    cudaFuncSetAttribute(gemm_tf32_kernel, cudaFuncAttributeMaxDynamicSharedMemorySize,
                         (int)GEMM_SMEM);
    cudaFuncSetAttribute(attn_kernel, cudaFuncAttributeMaxDynamicSharedMemorySize,
                         (int)ATT_SMEM);

    // 0) tf32-round weight copies (moves all cvt out of the GEMM hot loops)
    int wgrid = (E * E) / 1024;
    round_tf32_kernel<<<wgrid, 256>>>(Wq,   wq, E * E);
    round_tf32_kernel<<<wgrid, 256>>>(Wk,   wk, E * E);
    round_tf32_kernel<<<wgrid, 256>>>(Wv,   wv, E * E);
    round_tf32_kernel<<<wgrid, 256>>>(Wout, wo, E * E);

    // 1) pre-norm (output tf32-rounded)
    ln_kernel<<<T, 256, E * sizeof(float)>>>(x, h, norm_w, norm_b, E);

    // 2) Q/K/V projections; V output rounded (feeds PV mma directly)
    dim3 ggrid(E / GBN, T / GBM);
    gemm_tf32_kernel<<<ggrid, 256, GEMM_SMEM>>>(h, wq, qb, T, E, E, 0);
    gemm_tf32_kernel<<<ggrid, 256, GEMM_SMEM>>>(h, wk, kb, T, E, E, 0);
    gemm_tf32_kernel<<<ggrid, 256, GEMM_SMEM>>>(h, wv, vb, T, E, E, 1);

    // 3) q/k LayerNorm + RoPE (in-place, outputs tf32-rounded)
    lnrope_kernel<<<T, 256, E * sizeof(float)>>>(qb, lnq, cu, B, E);
    lnrope_kernel<<<T, 256, E * sizeof(float)>>>(kb, lnk, cu, B, E);

    // 4) attention
    dim3 agrid(S / QT_ROWS, NHEADS, B);
    attn_kernel<<<agrid, 256, ATT_SMEM>>>(qb, kb, vb, ob, S, E);

    // 5) output projection (plain fp32 output)
    gemm_tf32_kernel<<<ggrid, 256, GEMM_SMEM>>>(ob, wo, (float*)d_out, T, E, E, 0);
}